// round 1
// baseline (speedup 1.0000x reference)
#include <cuda_runtime.h>
#include <cuda_bf16.h>

// RelativeAttention: B=2,H=8,S=512,D=64
//   QK = q . k          [B,H,S,S]
//   QR = q . R[b,h,q,k] [B,H,S,S]   (R is 1.07 GB -> kernel is HBM-bound)
//   scores = (QK+QR)/8, mask(-1e9), softmax, mask(0)
//   out = p @ V
// Outputs concatenated in d_out: out [B,H,S,D] then p_attn [B,H,S,S].

#define Bc 2
#define Hc 8
#define Sc 512
#define Dc 64
#define TQ 8          // query rows per block (one per warp)
#define THREADS 256

__global__ __launch_bounds__(THREADS, 8)
void relattn_kernel(const float* __restrict__ Q, const float* __restrict__ K,
                    const float* __restrict__ V, const float* __restrict__ R,
                    const int* __restrict__ M,
                    float* __restrict__ out, float* __restrict__ p_out)
{
    __shared__ float q_sh[TQ][Dc];       // 2 KB
    __shared__ float p_sh[TQ][Sc];       // 16 KB

    const int qt   = blockIdx.x;         // q tile index
    const int h    = blockIdx.y;
    const int b    = blockIdx.z;
    const int tid  = threadIdx.x;
    const int w    = tid >> 5;           // warp = local query row
    const int lane = tid & 31;

    const int q0 = qt * TQ;
    const long bh = (long)b * Hc + h;

    const float* Qb = Q + (bh * Sc + q0) * Dc;
    const float* Kb = K + bh * Sc * Dc;
    const float* Vb = V + bh * Sc * Dc;
    const float* Rrow = R + ((bh * Sc + (long)(q0 + w)) * (long)Sc) * Dc; // R[b,h,qrow,0,0]
    const int*   Mrow = M + (((long)b * Sc + (q0 + w)) * Sc);             // mask[b,0,qrow,:]

    // ---- load Q tile into shared ----
    for (int i = tid; i < TQ * Dc; i += THREADS)
        q_sh[i / Dc][i % Dc] = Qb[i];
    __syncthreads();

    // ---- scores: each warp owns one query row; 16 lanes per k-row (float4) ----
    const int sub = lane >> 4;           // which of the 2 k-rows this half handles
    const int l16 = lane & 15;           // float4 index within the 64-float row
    const float4 q4 = ((const float4*)q_sh[w])[l16];

    #pragma unroll 4
    for (int it = 0; it < Sc / 2; ++it) {
        const int kk = it * 2 + sub;
        const float4 r4 = __ldg((const float4*)(Rrow + (long)kk * Dc) + l16);
        const float4 k4 = __ldg((const float4*)(Kb   + (long)kk * Dc) + l16);
        float s = q4.x * (r4.x + k4.x) + q4.y * (r4.y + k4.y)
                + q4.z * (r4.z + k4.z) + q4.w * (r4.w + k4.w);
        // reduce across the 16 lanes of each half-warp
        s += __shfl_xor_sync(0xffffffffu, s, 8);
        s += __shfl_xor_sync(0xffffffffu, s, 4);
        s += __shfl_xor_sync(0xffffffffu, s, 2);
        s += __shfl_xor_sync(0xffffffffu, s, 1);
        if (l16 == 0) p_sh[w][kk] = s * 0.125f;   // 1/sqrt(64)
    }
    __syncwarp();

    // ---- masked softmax, per warp over its 512 scores ----
    float vals[Sc / 32];
    float mx = -3.0e38f;
    #pragma unroll
    for (int i = 0; i < Sc / 32; ++i) {
        const int kk = lane + 32 * i;
        float s = p_sh[w][kk];
        s = (Mrow[kk] == 0) ? -1e9f : s;
        vals[i] = s;
        mx = fmaxf(mx, s);
    }
    #pragma unroll
    for (int o = 16; o; o >>= 1) mx = fmaxf(mx, __shfl_xor_sync(0xffffffffu, mx, o));
    float sum = 0.f;
    #pragma unroll
    for (int i = 0; i < Sc / 32; ++i) {
        const float e = expf(vals[i] - mx);
        vals[i] = e;
        sum += e;
    }
    #pragma unroll
    for (int o = 16; o; o >>= 1) sum += __shfl_xor_sync(0xffffffffu, sum, o);
    const float inv = 1.0f / sum;

    float* prow = p_out + (bh * Sc + (long)(q0 + w)) * Sc;
    #pragma unroll
    for (int i = 0; i < Sc / 32; ++i) {
        const int kk = lane + 32 * i;
        const float p = (Mrow[kk] == 0) ? 0.f : vals[i] * inv;
        p_sh[w][kk] = p;
        prow[kk] = p;            // coalesced 128B stores per warp
    }
    __syncwarp();

    // ---- AV: out[qrow,:] = sum_k p[k] * V[k,:]; lane covers 2 d-values ----
    float2 acc = make_float2(0.f, 0.f);
    #pragma unroll 4
    for (int kk = 0; kk < Sc; ++kk) {
        const float p = p_sh[w][kk];
        const float2 vv = ((const float2*)(Vb + (long)kk * Dc))[lane];
        acc.x += p * vv.x;
        acc.y += p * vv.y;
    }
    float* orow = out + (bh * Sc + (long)(q0 + w)) * Dc;
    ((float2*)orow)[lane] = acc;
}

extern "C" void kernel_launch(void* const* d_in, const int* in_sizes, int n_in,
                              void* d_out, int out_size)
{
    const float* Q = (const float*)d_in[0];
    const float* K = (const float*)d_in[1];
    const float* V = (const float*)d_in[2];
    const float* R = (const float*)d_in[3];
    const int*   M = (const int*)d_in[4];

    float* out   = (float*)d_out;                    // [B,H,S,D]
    float* p_out = out + (long)Bc * Hc * Sc * Dc;    // [B,H,S,S] appended

    dim3 grid(Sc / TQ, Hc, Bc);
    relattn_kernel<<<grid, THREADS>>>(Q, K, V, R, M, out, p_out);
}

// round 2
// speedup vs baseline: 1.1800x; 1.1800x over previous
#include <cuda_runtime.h>
#include <cuda_bf16.h>

// RelativeAttention: B=2,H=8,S=512,D=64
// scores = (Q.K + Q.R[q,k]) / 8, masked(-1e9), softmax, masked(0), out = p @ V
// KEY: masked (q,k) never need their R row -> skip ~50% of the 1.07GB R stream.
// Outputs concatenated in d_out: out [B,H,S,D] then p_attn [B,H,S,S].

#define Bc 2
#define Hc 8
#define Sc 512
#define Dc 64
#define TQ 8          // query rows per block (one per warp)
#define THREADS 256
#define FULLM 0xffffffffu

__global__ __launch_bounds__(THREADS, 8)
void relattn_kernel(const float* __restrict__ Q, const float* __restrict__ K,
                    const float* __restrict__ V, const float* __restrict__ R,
                    const int* __restrict__ M,
                    float* __restrict__ out, float* __restrict__ p_out)
{
    __shared__ float q_sh[TQ][Dc];                 // 2 KB
    __shared__ float p_sh[TQ][Sc];                 // 16 KB
    __shared__ unsigned short idx_sh[TQ][Sc];      // 8 KB (compacted unmasked k)

    const int qt   = blockIdx.x;
    const int h    = blockIdx.y;
    const int b    = blockIdx.z;
    const int tid  = threadIdx.x;
    const int w    = tid >> 5;                     // warp = local query row
    const int lane = tid & 31;

    const int q0 = qt * TQ;
    const int qrow = q0 + w;
    const long bh = (long)b * Hc + h;

    const float* Qb   = Q + (bh * Sc + q0) * Dc;
    const float* Kb   = K + bh * Sc * Dc;
    const float* Vb   = V + bh * Sc * Dc;
    const float* Rrow = R + ((bh * Sc + (long)qrow) * (long)Sc) * Dc;
    const int*   Mrow = M + (((long)b * Sc + qrow) * Sc);

    // ---- load Q tile ----
    for (int i = tid; i < TQ * Dc; i += THREADS)
        q_sh[i / Dc][i % Dc] = Qb[i];
    __syncthreads();

    // ---- per-warp mask compaction: dense list of unmasked k indices ----
    int cnt = 0;
    #pragma unroll
    for (int i = 0; i < Sc / 32; ++i) {
        const int kk = i * 32 + lane;
        const bool m = (Mrow[kk] != 0);
        const unsigned bal = __ballot_sync(FULLM, m);
        const int pos = cnt + __popc(bal & ((1u << lane) - 1u));
        if (m) idx_sh[w][pos] = (unsigned short)kk;
        cnt += __popc(bal);
    }
    __syncwarp();

    const int sub = lane >> 4;           // half-warp handles one k-row
    const int l16 = lane & 15;           // float4 slot within the 64-float row
    const float4 q4 = ((const float4*)q_sh[w])[l16];

    // ---- pass 1: QK for all 512 k (K is tiny: L1/L2-hot) ----
    #pragma unroll 4
    for (int it = 0; it < Sc / 2; ++it) {
        const int kk = it * 2 + sub;
        const float4 k4 = __ldg((const float4*)(Kb + (long)kk * Dc) + l16);
        float s = q4.x * k4.x + q4.y * k4.y + q4.z * k4.z + q4.w * k4.w;
        s += __shfl_xor_sync(FULLM, s, 8);
        s += __shfl_xor_sync(FULLM, s, 4);
        s += __shfl_xor_sync(FULLM, s, 2);
        s += __shfl_xor_sync(FULLM, s, 1);
        if (l16 == 0) p_sh[w][kk] = s;
    }
    __syncwarp();

    // ---- pass 2: stream R ONLY for unmasked k (evict-first: touch-once data) ----
    #pragma unroll 4
    for (int j = 0; j < cnt; j += 2) {
        const int jj = j + sub;
        const bool act = (jj < cnt);
        const int kk = act ? (int)idx_sh[w][jj] : 0;
        float4 r4 = make_float4(0.f, 0.f, 0.f, 0.f);
        if (act) r4 = __ldcs((const float4*)(Rrow + (long)kk * Dc) + l16);
        float s = q4.x * r4.x + q4.y * r4.y + q4.z * r4.z + q4.w * r4.w;
        s += __shfl_xor_sync(FULLM, s, 8);
        s += __shfl_xor_sync(FULLM, s, 4);
        s += __shfl_xor_sync(FULLM, s, 2);
        s += __shfl_xor_sync(FULLM, s, 1);
        if (l16 == 0 && act) p_sh[w][kk] += s;
    }
    __syncwarp();

    // ---- masked softmax over the warp's 512 scores ----
    float vals[Sc / 32];
    float mx = -3.0e38f;
    #pragma unroll
    for (int i = 0; i < Sc / 32; ++i) {
        const int kk = lane + 32 * i;
        float s = p_sh[w][kk] * 0.125f;           // 1/sqrt(64)
        s = (Mrow[kk] == 0) ? -1e9f : s;
        vals[i] = s;
        mx = fmaxf(mx, s);
    }
    #pragma unroll
    for (int o = 16; o; o >>= 1) mx = fmaxf(mx, __shfl_xor_sync(FULLM, mx, o));
    float sum = 0.f;
    #pragma unroll
    for (int i = 0; i < Sc / 32; ++i) {
        const float e = expf(vals[i] - mx);
        vals[i] = e;
        sum += e;
    }
    #pragma unroll
    for (int o = 16; o; o >>= 1) sum += __shfl_xor_sync(FULLM, sum, o);
    const float inv = 1.0f / sum;

    float* prow = p_out + (bh * Sc + (long)qrow) * Sc;
    #pragma unroll
    for (int i = 0; i < Sc / 32; ++i) {
        const int kk = lane + 32 * i;
        const float p = (Mrow[kk] == 0) ? 0.f : vals[i] * inv;
        p_sh[w][kk] = p;
        __stcs(prow + kk, p);                     // write-once: don't pollute L2
    }
    __syncwarp();

    // ---- AV over compacted indices only (p==0 elsewhere) ----
    float2 acc = make_float2(0.f, 0.f);
    #pragma unroll 4
    for (int j = 0; j < cnt; ++j) {
        const int kk = (int)idx_sh[w][j];
        const float p = p_sh[w][kk];
        const float2 vv = __ldg((const float2*)(Vb + (long)kk * Dc) + lane);
        acc.x += p * vv.x;
        acc.y += p * vv.y;
    }
    float* orow = out + (bh * Sc + (long)qrow) * Dc;
    ((float2*)orow)[lane] = acc;
}

extern "C" void kernel_launch(void* const* d_in, const int* in_sizes, int n_in,
                              void* d_out, int out_size)
{
    const float* Q = (const float*)d_in[0];
    const float* K = (const float*)d_in[1];
    const float* V = (const float*)d_in[2];
    const float* R = (const float*)d_in[3];
    const int*   M = (const int*)d_in[4];

    float* out   = (float*)d_out;                    // [B,H,S,D]
    float* p_out = out + (long)Bc * Hc * Sc * Dc;    // [B,H,S,S] appended

    dim3 grid(Sc / TQ, Hc, Bc);
    relattn_kernel<<<grid, THREADS>>>(Q, K, V, R, M, out, p_out);
}

// round 3
// speedup vs baseline: 1.7609x; 1.4922x over previous
#include <cuda_runtime.h>
#include <cuda_bf16.h>

// RelativeAttention: B=2,H=8,S=512,D=64
// scores = (Q.K + Q.R[q,k]) / 8, masked(-1e9), softmax, masked(0), out = p @ V
// Masked (q,k) need NEITHER their R row NOR their K dot -> single fused pass
// over the compacted unmasked index list (~50% of R's 1.07GB skipped).
// Outputs concatenated in d_out: out [B,H,S,D] then p_attn [B,H,S,S].

#define Bc 2
#define Hc 8
#define Sc 512
#define Dc 64
#define TQ 8          // query rows per block (one per warp)
#define THREADS 256
#define FULLM 0xffffffffu

__global__ __launch_bounds__(THREADS, 4)   // 64-reg budget -> deep LDG batching
void relattn_kernel(const float* __restrict__ Q, const float* __restrict__ K,
                    const float* __restrict__ V, const float* __restrict__ R,
                    const int* __restrict__ M,
                    float* __restrict__ out, float* __restrict__ p_out)
{
    __shared__ float q_sh[TQ][Dc];                   // 2 KB
    __shared__ float p_sh[TQ][Sc];                   // 16 KB
    __shared__ unsigned short idx_sh[TQ][Sc + 8];    // compacted unmasked k (+pad)

    const int qt   = blockIdx.x;
    const int h    = blockIdx.y;
    const int b    = blockIdx.z;
    const int tid  = threadIdx.x;
    const int w    = tid >> 5;
    const int lane = tid & 31;

    const int q0 = qt * TQ;
    const int qrow = q0 + w;
    const long bh = (long)b * Hc + h;

    const float* Qb   = Q + (bh * Sc + q0) * Dc;
    const float* Kb   = K + bh * Sc * Dc;
    const float* Vb   = V + bh * Sc * Dc;
    const float* Rrow = R + ((bh * Sc + (long)qrow) * (long)Sc) * Dc;
    const int*   Mrow = M + (((long)b * Sc + qrow) * Sc);

    for (int i = tid; i < TQ * Dc; i += THREADS)
        q_sh[i / Dc][i % Dc] = Qb[i];
    __syncthreads();

    // ---- per-warp mask compaction; keep mask bits in registers ----
    unsigned mbits[Sc / 32];
    int cnt = 0;
    #pragma unroll
    for (int i = 0; i < Sc / 32; ++i) {
        const int kk = i * 32 + lane;
        const bool m = (__ldg(Mrow + kk) != 0);
        const unsigned bal = __ballot_sync(FULLM, m);
        mbits[i] = bal;
        const int pos = cnt + __popc(bal & ((1u << lane) - 1u));
        if (m) idx_sh[w][pos] = (unsigned short)kk;
        cnt += __popc(bal);
    }
    __syncwarp();
    if (lane < 8) idx_sh[w][cnt + lane] = (cnt > 0) ? idx_sh[w][0] : (unsigned short)0;
    __syncwarp();

    // ---- fused scores pass: q . (R_k + K_k) for unmasked k only ----
    const int rg = lane >> 3;            // row within group of 4
    const int l8 = lane & 7;             // float4 slot within first half-row
    const float4 qa = ((const float4*)q_sh[w])[l8];
    const float4 qb = ((const float4*)q_sh[w])[l8 + 8];

    const int cnt4 = (cnt + 3) & ~3;
    #pragma unroll 2
    for (int j = 0; j < cnt4; j += 4) {
        const int jj = j + rg;
        const int kk = (int)idx_sh[w][jj];               // pad-safe address
        const float* rrow = Rrow + (long)kk * Dc;
        const float* krow = Kb   + (long)kk * Dc;
        const float4 ra = __ldcs((const float4*)rrow + l8);
        const float4 rb = __ldcs((const float4*)rrow + l8 + 8);
        const float4 ka = __ldg((const float4*)krow + l8);
        const float4 kb = __ldg((const float4*)krow + l8 + 8);
        float s = qa.x * (ra.x + ka.x) + qa.y * (ra.y + ka.y)
                + qa.z * (ra.z + ka.z) + qa.w * (ra.w + ka.w)
                + qb.x * (rb.x + kb.x) + qb.y * (rb.y + kb.y)
                + qb.z * (rb.z + kb.z) + qb.w * (rb.w + kb.w);
        s += __shfl_xor_sync(FULLM, s, 4);
        s += __shfl_xor_sync(FULLM, s, 2);
        s += __shfl_xor_sync(FULLM, s, 1);
        if (l8 == 0 && jj < cnt) p_sh[w][kk] = s;
    }
    __syncwarp();

    // ---- masked softmax (p_sh garbage at masked kk is selected away) ----
    float vals[Sc / 32];
    float mx = -3.0e38f;
    #pragma unroll
    for (int i = 0; i < Sc / 32; ++i) {
        const int kk = lane + 32 * i;
        const bool um = (mbits[i] >> lane) & 1u;
        float s = um ? p_sh[w][kk] * 0.125f : -1e9f;
        vals[i] = s;
        mx = fmaxf(mx, s);
    }
    #pragma unroll
    for (int o = 16; o; o >>= 1) mx = fmaxf(mx, __shfl_xor_sync(FULLM, mx, o));
    float sum = 0.f;
    #pragma unroll
    for (int i = 0; i < Sc / 32; ++i) {
        const float e = __expf(vals[i] - mx);
        vals[i] = e;
        sum += e;
    }
    #pragma unroll
    for (int o = 16; o; o >>= 1) sum += __shfl_xor_sync(FULLM, sum, o);
    const float inv = 1.0f / sum;

    float* prow = p_out + (bh * Sc + (long)qrow) * Sc;
    #pragma unroll
    for (int i = 0; i < Sc / 32; ++i) {
        const int kk = lane + 32 * i;
        const bool um = (mbits[i] >> lane) & 1u;
        const float p = um ? vals[i] * inv : 0.f;
        p_sh[w][kk] = p;
        __stcs(prow + kk, p);
    }
    __syncwarp();

    // ---- AV over compacted indices, 4 accumulators ----
    float2 acc0 = make_float2(0.f, 0.f), acc1 = make_float2(0.f, 0.f);
    const int cnt2 = (cnt + 1) & ~1;
    #pragma unroll 4
    for (int j = 0; j < cnt2; j += 2) {
        const int k0 = (int)idx_sh[w][j];
        const int k1 = (int)idx_sh[w][j + 1];
        const float p0 = p_sh[w][k0];
        const float p1 = (j + 1 < cnt) ? p_sh[w][k1] : 0.f;
        const float2 v0 = __ldg((const float2*)(Vb + (long)k0 * Dc) + lane);
        const float2 v1 = __ldg((const float2*)(Vb + (long)k1 * Dc) + lane);
        acc0.x += p0 * v0.x; acc0.y += p0 * v0.y;
        acc1.x += p1 * v1.x; acc1.y += p1 * v1.y;
    }
    float* orow = out + (bh * Sc + (long)qrow) * Dc;
    ((float2*)orow)[lane] = make_float2(acc0.x + acc1.x, acc0.y + acc1.y);
}

extern "C" void kernel_launch(void* const* d_in, const int* in_sizes, int n_in,
                              void* d_out, int out_size)
{
    const float* Q = (const float*)d_in[0];
    const float* K = (const float*)d_in[1];
    const float* V = (const float*)d_in[2];
    const float* R = (const float*)d_in[3];
    const int*   M = (const int*)d_in[4];

    float* out   = (float*)d_out;                    // [B,H,S,D]
    float* p_out = out + (long)Bc * Hc * Sc * Dc;    // [B,H,S,S] appended

    dim3 grid(Sc / TQ, Hc, Bc);
    relattn_kernel<<<grid, THREADS>>>(Q, K, V, R, M, out, p_out);
}